// round 3
// baseline (speedup 1.0000x reference)
#include <cuda_runtime.h>
#include <cstdint>

// Problem constants (fixed by the reference):
//   x: (B=512, HIDDEN=512, 1, SEQ=256) fp32, SEQ = BLOCK(16) * GROUPS(16)
//   W: (HIDDEN, 16, 16) fp32
//   y[b,h,o,g] = sum_i W[h,o,i] * x[b,h,i,g]
// Per (b,h): y(16x16) = W(16x16) @ X(16x16), X[i][g] contiguous in g.

#define HIDDEN_C 512
#define SEQ_C    256   // 16 i * 16 g, g fastest
#define HB       16    // h per block
#define BB       8     // b per block
#define WPAD     260   // padded per-h stride in shared (floats): 256 + 4 kills 2-way bank conflict

__global__ __launch_bounds__(256)
void global_mixer_kernel(const float* __restrict__ x,
                         const float* __restrict__ W,
                         float* __restrict__ y)
{
    __shared__ float sWt[HB * WPAD];   // sWt[hl*WPAD + i*16 + o] = W[h0+hl][o][i]

    const int t  = threadIdx.x;        // 256 threads
    const int h0 = blockIdx.x * HB;    // 16 h per block (gridDim.x = HIDDEN/16 = 32)

    // ---- Stage W transposed into shared ----
    // thread t -> (hl = t/16, o = t%16) owns one W row of 16 floats (contiguous).
    {
        const int hl = t >> 4;
        const int o  = t & 15;
        const float4* wr =
            reinterpret_cast<const float4*>(W + ((size_t)(h0 + hl)) * 256 + (size_t)o * 16);
        float4 w0 = wr[0], w1 = wr[1], w2 = wr[2], w3 = wr[3];
        float wrow[16] = { w0.x, w0.y, w0.z, w0.w,
                           w1.x, w1.y, w1.z, w1.w,
                           w2.x, w2.y, w2.z, w2.w,
                           w3.x, w3.y, w3.z, w3.w };
        float* dst = &sWt[hl * WPAD + o];
        #pragma unroll
        for (int i = 0; i < 16; i++)
            dst[i * 16] = wrow[i];
    }
    __syncthreads();

    // ---- Compute: thread owns one (h, g) column, loops over BB batches ----
    const int hl = t >> 4;             // h within block
    const int g  = t & 15;             // group/column index
    const float* wbase = &sWt[hl * WPAD];

    // base offset of x/y for (b = blockIdx.y*BB, h = h0+hl), element g
    size_t base = ((size_t)blockIdx.y * BB * HIDDEN_C + (size_t)(h0 + hl)) * SEQ_C + (size_t)g;
    const size_t bstride = (size_t)HIDDEN_C * SEQ_C;   // advance one b

    #pragma unroll 1
    for (int bi = 0; bi < BB; bi++) {
        const float* xp = x + base + (size_t)bi * bstride;
        float*       yp = y + base + (size_t)bi * bstride;

        // Hoist all 16 input loads -> MLP ~16
        float xv[16];
        #pragma unroll
        for (int i = 0; i < 16; i++)
            xv[i] = xp[i * 16];

        float acc[16];
        #pragma unroll
        for (int o = 0; o < 16; o++)
            acc[o] = 0.0f;

        #pragma unroll
        for (int i = 0; i < 16; i++) {
            // W column i (all 16 o), broadcast LDS.128 x4
            const float4* wcol = reinterpret_cast<const float4*>(wbase + i * 16);
            #pragma unroll
            for (int o4 = 0; o4 < 4; o4++) {
                float4 w = wcol[o4];
                acc[4 * o4 + 0] = fmaf(w.x, xv[i], acc[4 * o4 + 0]);
                acc[4 * o4 + 1] = fmaf(w.y, xv[i], acc[4 * o4 + 1]);
                acc[4 * o4 + 2] = fmaf(w.z, xv[i], acc[4 * o4 + 2]);
                acc[4 * o4 + 3] = fmaf(w.w, xv[i], acc[4 * o4 + 3]);
            }
        }

        #pragma unroll
        for (int o = 0; o < 16; o++)
            yp[o * 16] = acc[o];
    }
}

extern "C" void kernel_launch(void* const* d_in, const int* in_sizes, int n_in,
                              void* d_out, int out_size)
{
    const float* x = (const float*)d_in[0];   // (512, 512, 1, 256) fp32
    const float* W = (const float*)d_in[1];   // (512, 16, 16) fp32
    float* y = (float*)d_out;

    const int B = in_sizes[0] / (HIDDEN_C * SEQ_C);   // 512

    dim3 grid(HIDDEN_C / HB, B / BB);   // (32, 64)
    dim3 block(256);
    global_mixer_kernel<<<grid, block>>>(x, W, y);
}

// round 5
// speedup vs baseline: 7.7074x; 7.7074x over previous
#include <cuda_runtime.h>
#include <cstdint>

// y[b,h,o,g] = sum_i W[h,o,i] * x[b,h,i,g]
// x: (B=512, HIDDEN=512, SEQ=256) fp32 ; per (b,h) tile: 16 i x 16 g, g fastest, 1 KB contiguous.
// W: (HIDDEN, 16, 16) fp32.
//
// R3 strategy: all HBM traffic as long contiguous float4 bursts (16 KB per chunk),
// strided 64B access pattern moved into padded shared memory.

#define HIDDEN_C 512
#define SEQ_C    256
#define HB       16          // h per block (one chunk = 16 h tiles = 16 KB)
#define BB       8           // chunks (b values) per block
#define WPAD     260         // per-h W stride in smem: 260 % 32 == 4  -> disjoint banks for 2 h-halves
#define XPAD     272         // per-tile x/y stride in smem: 272 % 32 == 16 -> disjoint bank halves
#define XPAD4    (XPAD/4)    // 68, float4 stride

__global__ __launch_bounds__(256)
void global_mixer_kernel(const float* __restrict__ x,
                         const float* __restrict__ W,
                         float* __restrict__ y)
{
    __shared__ __align__(16) float sWt[HB * WPAD];   // sWt[hl*WPAD + i*16 + o] = W[h][o][i]
    __shared__ __align__(16) float sBuf[HB * XPAD];  // reused: x chunk, then y chunk

    const int t  = threadIdx.x;          // 256
    const int h0 = blockIdx.x * HB;

    // ---- Stage W transposed (once per CTA) ----
    {
        const int hl = t >> 4;
        const int o  = t & 15;
        const float4* wr =
            reinterpret_cast<const float4*>(W + ((size_t)(h0 + hl)) * 256 + (size_t)o * 16);
        float4 w0 = wr[0], w1 = wr[1], w2 = wr[2], w3 = wr[3];
        float wrow[16] = { w0.x, w0.y, w0.z, w0.w,
                           w1.x, w1.y, w1.z, w1.w,
                           w2.x, w2.y, w2.z, w2.w,
                           w3.x, w3.y, w3.z, w3.w };
        float* dst = &sWt[hl * WPAD + o];
        #pragma unroll
        for (int i = 0; i < 16; i++)
            dst[i * 16] = wrow[i];
    }
    __syncthreads();

    const int hl = t >> 4;
    const int g  = t & 15;
    const float* wb = &sWt[hl * WPAD];
    float*       cb = &sBuf[hl * XPAD + g];   // this thread's strided column in the chunk buffer

    #pragma unroll 1
    for (int bi = 0; bi < BB; bi++) {
        const size_t b  = (size_t)blockIdx.y * BB + bi;
        const size_t gb = (b * HIDDEN_C + (size_t)h0) * SEQ_C;   // chunk base (16 KB contiguous)
        const float4* xg = reinterpret_cast<const float4*>(x + gb);
        float4*       yg = reinterpret_cast<float4*>(y + gb);
        float4*       s4 = reinterpret_cast<float4*>(sBuf);

        // ---- Cooperative load: 16 KB contiguous, 512 B per warp instruction ----
        #pragma unroll
        for (int j = 0; j < 4; j++) {
            int q = j * 256 + t;                       // float4 index within chunk, 0..1023
            s4[(q >> 6) * XPAD4 + (q & 63)] = xg[q];   // tile = q/64, padded layout
        }
        __syncthreads();

        // ---- Compute: thread owns (hl, g) column; 16x16 matvec from smem ----
        float acc[16];
        #pragma unroll
        for (int o = 0; o < 16; o++) acc[o] = 0.0f;

        #pragma unroll
        for (int i = 0; i < 16; i++) {
            float xv = cb[i * 16];                                 // conflict-free (XPAD pad)
            const float4* wcol = reinterpret_cast<const float4*>(wb + i * 16);
            #pragma unroll
            for (int o4 = 0; o4 < 4; o4++) {
                float4 w = wcol[o4];                               // broadcast, 2 bank-disjoint addrs
                acc[4 * o4 + 0] = fmaf(w.x, xv, acc[4 * o4 + 0]);
                acc[4 * o4 + 1] = fmaf(w.y, xv, acc[4 * o4 + 1]);
                acc[4 * o4 + 2] = fmaf(w.z, xv, acc[4 * o4 + 2]);
                acc[4 * o4 + 3] = fmaf(w.w, xv, acc[4 * o4 + 3]);
            }
        }
        __syncthreads();   // all sBuf reads done before overwrite

        // ---- Write results into the same buffer ----
        #pragma unroll
        for (int o = 0; o < 16; o++)
            cb[o * 16] = acc[o];
        __syncthreads();

        // ---- Cooperative store: 16 KB contiguous ----
        #pragma unroll
        for (int j = 0; j < 4; j++) {
            int q = j * 256 + t;
            yg[q] = s4[(q >> 6) * XPAD4 + (q & 63)];
        }
        __syncthreads();   // protect sBuf before next chunk's load
    }
}

extern "C" void kernel_launch(void* const* d_in, const int* in_sizes, int n_in,
                              void* d_out, int out_size)
{
    const float* x = (const float*)d_in[0];   // (B, 512, 1, 256) fp32
    const float* W = (const float*)d_in[1];   // (512, 16, 16) fp32
    float* y = (float*)d_out;

    const int B = in_sizes[0] / (HIDDEN_C * SEQ_C);   // 512

    dim3 grid(HIDDEN_C / HB, B / BB);   // (32, 64)
    global_mixer_kernel<<<grid, 256>>>(x, W, y);
}

// round 8
// speedup vs baseline: 9.8429x; 1.2771x over previous
#include <cuda_runtime.h>
#include <cstdint>

// y[b,h,o,g] = sum_i W[h,o,i] * x[b,h,i,g]
// x: (B=512, HIDDEN=512, SEQ=256) fp32; per (b,h) tile 16 i x 16 g, g fastest (1 KB).
// W: (HIDDEN, 16, 16) fp32.
//
// R5: 4x4 register tile per thread (h, o-quad, g-quad) -> per i-step just
// 2 conflict-free LDS.128 + 16 FMA. Input staged through smem as 16 KB
// contiguous bursts; output written directly with sector-dense STG.128.

#define HIDDEN_C 512
#define SEQ_C    256
#define HB       16          // h per block (chunk = 16 KB)
#define BB       8           // b-chunks per block
#define TPAD     272         // smem tile stride in floats; 272/4=68 ==4 mod 8 bank-groups
#define TPAD4    68

__global__ __launch_bounds__(256)
void global_mixer_kernel(const float* __restrict__ x,
                         const float* __restrict__ W,
                         float* __restrict__ y)
{
    __shared__ __align__(16) float sWt[HB * TPAD];   // sWt[hl][i][o], o fastest
    __shared__ __align__(16) float sX [HB * TPAD];   // sX [hl][i][g], g fastest

    const int t  = threadIdx.x;            // 256
    const int h0 = blockIdx.x * HB;

    // ---- Stage W transposed: sWt[hl*TPAD + i*16 + o] = W[h0+hl][o][i] ----
    {
        const int hl = t >> 4;
        const int o  = t & 15;
        const float4* wr =
            reinterpret_cast<const float4*>(W + ((size_t)(h0 + hl)) * 256 + (size_t)o * 16);
        float4 w0 = wr[0], w1 = wr[1], w2 = wr[2], w3 = wr[3];
        float wrow[16] = { w0.x, w0.y, w0.z, w0.w,
                           w1.x, w1.y, w1.z, w1.w,
                           w2.x, w2.y, w2.z, w2.w,
                           w3.x, w3.y, w3.z, w3.w };
        float* dst = &sWt[hl * TPAD + o];
        #pragma unroll
        for (int i = 0; i < 16; i++)
            dst[i * 16] = wrow[i];          // banks (16*hl + o) % 32: conflict-free
    }
    __syncthreads();

    // thread -> (hl, oq, gq): 16 x 4 x 4
    const int gq = t & 3;
    const int oq = (t >> 2) & 3;
    const int hl = t >> 4;

    const float4* w4 = reinterpret_cast<const float4*>(sWt) + hl * TPAD4 + oq;  // + i*4
    const float4* x4 = reinterpret_cast<const float4*>(sX)  + hl * TPAD4 + gq;  // + i*4
    float4* s4 = reinterpret_cast<float4*>(sX);

    #pragma unroll 1
    for (int bi = 0; bi < BB; bi++) {
        const size_t b  = (size_t)blockIdx.y * BB + bi;
        const size_t gb = (b * HIDDEN_C + (size_t)h0) * SEQ_C;   // 16 KB contiguous chunk
        const float4* xg = reinterpret_cast<const float4*>(x + gb);
        float*        yg = y + gb;

        // ---- Stage x chunk: 16 KB contiguous in, padded layout in smem ----
        #pragma unroll
        for (int j = 0; j < 4; j++) {
            int q = j * 256 + t;                        // float4 index 0..1023
            s4[(q >> 6) * TPAD4 + (q & 63)] = xg[q];    // tile q/64
        }
        __syncthreads();

        // ---- 4x4 register-tile matmul ----
        float acc[4][4];
        #pragma unroll
        for (int r = 0; r < 4; r++)
            #pragma unroll
            for (int c = 0; c < 4; c++)
                acc[r][c] = 0.0f;

        #pragma unroll
        for (int i = 0; i < 16; i++) {
            float4 wv = w4[i * 4];   // W[hl][i][4oq..4oq+3]  (conflict-free)
            float4 xv = x4[i * 4];   // x[hl][i][4gq..4gq+3]  (conflict-free)
            acc[0][0] = fmaf(wv.x, xv.x, acc[0][0]);
            acc[0][1] = fmaf(wv.x, xv.y, acc[0][1]);
            acc[0][2] = fmaf(wv.x, xv.z, acc[0][2]);
            acc[0][3] = fmaf(wv.x, xv.w, acc[0][3]);
            acc[1][0] = fmaf(wv.y, xv.x, acc[1][0]);
            acc[1][1] = fmaf(wv.y, xv.y, acc[1][1]);
            acc[1][2] = fmaf(wv.y, xv.z, acc[1][2]);
            acc[1][3] = fmaf(wv.y, xv.w, acc[1][3]);
            acc[2][0] = fmaf(wv.z, xv.x, acc[2][0]);
            acc[2][1] = fmaf(wv.z, xv.y, acc[2][1]);
            acc[2][2] = fmaf(wv.z, xv.z, acc[2][2]);
            acc[2][3] = fmaf(wv.z, xv.w, acc[2][3]);
            acc[3][0] = fmaf(wv.w, xv.x, acc[3][0]);
            acc[3][1] = fmaf(wv.w, xv.y, acc[3][1]);
            acc[3][2] = fmaf(wv.w, xv.z, acc[3][2]);
            acc[3][3] = fmaf(wv.w, xv.w, acc[3][3]);
        }

        // ---- Direct store: thread writes rows o=4oq+r, cols 4gq..4gq+3.
        // 4 gq-lanes cover each 64 B row fully -> sector-dense STG.128.
        {
            float* ybase = yg + (size_t)hl * 256 + (size_t)(4 * oq) * 16 + (size_t)(4 * gq);
            #pragma unroll
            for (int r = 0; r < 4; r++) {
                float4 v = make_float4(acc[r][0], acc[r][1], acc[r][2], acc[r][3]);
                *reinterpret_cast<float4*>(ybase + r * 16) = v;
            }
        }
        __syncthreads();   // all sX reads done before next chunk overwrites
    }
}

extern "C" void kernel_launch(void* const* d_in, const int* in_sizes, int n_in,
                              void* d_out, int out_size)
{
    const float* x = (const float*)d_in[0];   // (B, 512, 1, 256) fp32
    const float* W = (const float*)d_in[1];   // (512, 16, 16) fp32
    float* y = (float*)d_out;

    const int B = in_sizes[0] / (HIDDEN_C * SEQ_C);   // 512

    dim3 grid(HIDDEN_C / HB, B / BB);   // (32, 64)
    global_mixer_kernel<<<grid, 256>>>(x, W, y);
}

// round 9
// speedup vs baseline: 10.3628x; 1.0528x over previous
#include <cuda_runtime.h>
#include <cstdint>

// y[b,h,o,g] = sum_i W[h,o,i] * x[b,h,i,g]
// x: (B=512, HIDDEN=512, SEQ=256) fp32; per (b,h) tile 16 i x 16 g, g fastest (1 KB).
// W: (HIDDEN, 16, 16) fp32.
//
// R8: W register-cached (64 regs/thread, loaded once per CTA) -> compute does
// only 16 x-LDS.128 per warp-chunk. Double-buffered smem x staging with a
// 1-sync pipeline; LDG for next chunk issued before current compute.

#define HIDDEN_C 512
#define SEQ_C    256
#define HB       16          // h per block (chunk = 16 KB)
#define BB       8           // b-chunks per block
#define TPAD     272         // smem tile stride (floats); 272/4=68 == 4 mod 8 bank-groups
#define TPAD4    68

__global__ __launch_bounds__(256, 2)
void global_mixer_kernel(const float* __restrict__ x,
                         const float* __restrict__ W,
                         float* __restrict__ y)
{
    __shared__ __align__(16) float sm[2][HB * TPAD];   // [0] first stages W^T, then x ping-pong

    const int t  = threadIdx.x;            // 256
    const int h0 = blockIdx.x * HB;

    const int gq = t & 3;
    const int oq = (t >> 2) & 3;
    const int hl = t >> 4;

    // ---- Stage W transposed into sm[0]: sm0[hl*TPAD + i*16 + o] = W[h0+hl][o][i] ----
    {
        const int shl = t >> 4;
        const int so  = t & 15;
        const float4* wr =
            reinterpret_cast<const float4*>(W + ((size_t)(h0 + shl)) * 256 + (size_t)so * 16);
        float4 w0 = wr[0], w1 = wr[1], w2 = wr[2], w3 = wr[3];
        float wrow[16] = { w0.x, w0.y, w0.z, w0.w,
                           w1.x, w1.y, w1.z, w1.w,
                           w2.x, w2.y, w2.z, w2.w,
                           w3.x, w3.y, w3.z, w3.w };
        float* dst = &sm[0][shl * TPAD + so];
        #pragma unroll
        for (int i = 0; i < 16; i++)
            dst[i * 16] = wrow[i];
    }
    __syncthreads();

    // ---- Pull this thread's W columns into registers: wreg[i] = W[h][4oq..4oq+3][i] ----
    float4 wreg[16];
    {
        const float4* wsrc = reinterpret_cast<const float4*>(sm[0]) + hl * TPAD4 + oq;
        #pragma unroll
        for (int i = 0; i < 16; i++)
            wreg[i] = wsrc[i * 4];         // conflict-free (TPAD pad)
    }
    __syncthreads();                        // sm[0] now free for x staging

    const size_t chunk0 = ((size_t)blockIdx.y * BB * HIDDEN_C + (size_t)h0) * SEQ_C;
    const size_t bstride = (size_t)HIDDEN_C * SEQ_C;

    // ---- Prologue: load chunk 0 and stage into sm[0] ----
    float4 xs[4];
    {
        const float4* xg = reinterpret_cast<const float4*>(x + chunk0);
        #pragma unroll
        for (int j = 0; j < 4; j++)
            xs[j] = xg[j * 256 + t];
        float4* s4 = reinterpret_cast<float4*>(sm[0]);
        #pragma unroll
        for (int j = 0; j < 4; j++) {
            int q = j * 256 + t;
            s4[(q >> 6) * TPAD4 + (q & 63)] = xs[j];
        }
    }
    __syncthreads();

    int cur = 0;

    #pragma unroll 1
    for (int bi = 0; bi < BB; bi++) {
        // ---- Prefetch next chunk into registers (DRAM latency hidden by compute) ----
        if (bi + 1 < BB) {
            const float4* xg =
                reinterpret_cast<const float4*>(x + chunk0 + (size_t)(bi + 1) * bstride);
            #pragma unroll
            for (int j = 0; j < 4; j++)
                xs[j] = xg[j * 256 + t];
        }

        // ---- Compute: 4x4 register tile, x from smem, W from registers ----
        const float4* x4 = reinterpret_cast<const float4*>(sm[cur]) + hl * TPAD4 + gq;

        float acc[4][4];
        #pragma unroll
        for (int r = 0; r < 4; r++)
            #pragma unroll
            for (int c = 0; c < 4; c++)
                acc[r][c] = 0.0f;

        #pragma unroll
        for (int i = 0; i < 16; i++) {
            float4 xv = x4[i * 4];          // conflict-free LDS.128
            float4 wv = wreg[i];
            acc[0][0] = fmaf(wv.x, xv.x, acc[0][0]);
            acc[0][1] = fmaf(wv.x, xv.y, acc[0][1]);
            acc[0][2] = fmaf(wv.x, xv.z, acc[0][2]);
            acc[0][3] = fmaf(wv.x, xv.w, acc[0][3]);
            acc[1][0] = fmaf(wv.y, xv.x, acc[1][0]);
            acc[1][1] = fmaf(wv.y, xv.y, acc[1][1]);
            acc[1][2] = fmaf(wv.y, xv.z, acc[1][2]);
            acc[1][3] = fmaf(wv.y, xv.w, acc[1][3]);
            acc[2][0] = fmaf(wv.z, xv.x, acc[2][0]);
            acc[2][1] = fmaf(wv.z, xv.y, acc[2][1]);
            acc[2][2] = fmaf(wv.z, xv.z, acc[2][2]);
            acc[2][3] = fmaf(wv.z, xv.w, acc[2][3]);
            acc[3][0] = fmaf(wv.w, xv.x, acc[3][0]);
            acc[3][1] = fmaf(wv.w, xv.y, acc[3][1]);
            acc[3][2] = fmaf(wv.w, xv.z, acc[3][2]);
            acc[3][3] = fmaf(wv.w, xv.w, acc[3][3]);
        }

        // ---- Direct sector-dense store: rows o=4oq+r, cols 4gq..4gq+3 ----
        {
            float* ybase = y + chunk0 + (size_t)bi * bstride
                         + (size_t)hl * 256 + (size_t)(4 * oq) * 16 + (size_t)(4 * gq);
            #pragma unroll
            for (int r = 0; r < 4; r++) {
                float4 v = make_float4(acc[r][0], acc[r][1], acc[r][2], acc[r][3]);
                *reinterpret_cast<float4*>(ybase + r * 16) = v;
            }
        }

        // ---- Stage prefetched chunk into the other buffer; single sync ----
        if (bi + 1 < BB) {
            float4* s4 = reinterpret_cast<float4*>(sm[cur ^ 1]);
            #pragma unroll
            for (int j = 0; j < 4; j++) {
                int q = j * 256 + t;
                s4[(q >> 6) * TPAD4 + (q & 63)] = xs[j];
            }
            __syncthreads();   // next buffer fully written; all reads of sm[cur] done
            cur ^= 1;
        }
    }
}

extern "C" void kernel_launch(void* const* d_in, const int* in_sizes, int n_in,
                              void* d_out, int out_size)
{
    const float* x = (const float*)d_in[0];   // (B, 512, 1, 256) fp32
    const float* W = (const float*)d_in[1];   // (512, 16, 16) fp32
    float* y = (float*)d_out;

    const int B = in_sizes[0] / (HIDDEN_C * SEQ_C);   // 512

    dim3 grid(HIDDEN_C / HB, B / BB);   // (32, 64)
    global_mixer_kernel<<<grid, 256>>>(x, W, y);
}

// round 11
// speedup vs baseline: 10.3662x; 1.0003x over previous
#include <cuda_runtime.h>
#include <cstdint>

// y[b,h,o,g] = sum_i W[h,o,i] * x[b,h,i,g]
// x: (B=512, HIDDEN=512, SEQ=256) fp32; per (b,h) tile 16 i x 16 g, g fastest (1 KB).
// W: (HIDDEN, 16, 16) fp32.
//
// R9: staging via cp.async.bulk (UBLKCP) + mbarrier complete_tx. Warp path does
// only compute LDS + STG. W register-cached (64 regs). Ring-2 smem buffers,
// one syncthreads + one mbarrier wait per chunk. Streaming stores.

#define HIDDEN_C 512
#define SEQ_C    256
#define HB       16          // h per block (chunk = 16 KB = 16 tiles x 1 KB)
#define BB       8           // b-chunks per block
#define TPAD     272         // smem tile stride (floats); 68 float4 == 4 mod 8 bank-groups
#define TPAD4    68
#define TILE_BYTES 1024u

__device__ __forceinline__ uint32_t smem_u32(const void* p) {
    uint32_t a;
    asm("{ .reg .u64 t; cvta.to.shared.u64 t, %1; cvt.u32.u64 %0, t; }" : "=r"(a) : "l"(p));
    return a;
}

__device__ __forceinline__ void mbar_init(uint32_t bar, uint32_t count) {
    asm volatile("mbarrier.init.shared.b64 [%0], %1;" :: "r"(bar), "r"(count) : "memory");
}

__device__ __forceinline__ void mbar_expect_tx(uint32_t bar, uint32_t bytes) {
    asm volatile("mbarrier.arrive.expect_tx.shared.b64 _, [%0], %1;"
                 :: "r"(bar), "r"(bytes) : "memory");
}

__device__ __forceinline__ void bulk_g2s(uint32_t dst, const void* src, uint32_t bytes,
                                         uint32_t bar) {
    asm volatile(
        "cp.async.bulk.shared::cluster.global.mbarrier::complete_tx::bytes "
        "[%0], [%1], %2, [%3];"
        :: "r"(dst), "l"(src), "r"(bytes), "r"(bar) : "memory");
}

__device__ __forceinline__ void mbar_wait(uint32_t bar, uint32_t parity) {
    asm volatile(
        "{\n\t"
        ".reg .pred P;\n\t"
        "W_%=:\n\t"
        "mbarrier.try_wait.parity.acquire.cta.shared::cta.b64 P, [%0], %1, 0x989680;\n\t"
        "@P bra D_%=;\n\t"
        "bra W_%=;\n\t"
        "D_%=:\n\t"
        "}"
        :: "r"(bar), "r"(parity) : "memory");
}

__global__ __launch_bounds__(256, 2)
void global_mixer_kernel(const float* __restrict__ x,
                         const float* __restrict__ W,
                         float* __restrict__ y)
{
    __shared__ __align__(16) float ring[2][HB * TPAD];
    __shared__ __align__(8)  unsigned long long full_bar[2];

    const int t  = threadIdx.x;            // 256
    const int h0 = blockIdx.x * HB;

    const int gq = t & 3;
    const int oq = (t >> 2) & 3;
    const int hl = t >> 4;

    // ---- Stage W transposed into ring[0]: [hl][i][o], o fastest ----
    {
        const int shl = t >> 4;
        const int so  = t & 15;
        const float4* wr =
            reinterpret_cast<const float4*>(W + ((size_t)(h0 + shl)) * 256 + (size_t)so * 16);
        float4 w0 = wr[0], w1 = wr[1], w2 = wr[2], w3 = wr[3];
        float wrow[16] = { w0.x, w0.y, w0.z, w0.w,
                           w1.x, w1.y, w1.z, w1.w,
                           w2.x, w2.y, w2.z, w2.w,
                           w3.x, w3.y, w3.z, w3.w };
        float* dst = &ring[0][shl * TPAD + so];
        #pragma unroll
        for (int i = 0; i < 16; i++)
            dst[i * 16] = wrow[i];
    }
    __syncthreads();

    // ---- wreg[i] = W[h0+hl][4oq..4oq+3][i] ----
    float4 wreg[16];
    {
        const float4* wsrc = reinterpret_cast<const float4*>(ring[0]) + hl * TPAD4 + oq;
        #pragma unroll
        for (int i = 0; i < 16; i++)
            wreg[i] = wsrc[i * 4];
    }
    __syncthreads();                        // ring[0] free for x

    // ---- mbarriers: 16 arrivals (one expect_tx per issuing thread) ----
    const uint32_t bar0 = smem_u32(&full_bar[0]);
    const uint32_t bar1 = smem_u32(&full_bar[1]);
    if (t == 0) { mbar_init(bar0, 16); mbar_init(bar1, 16); }
    __syncthreads();

    const size_t chunk0  = ((size_t)blockIdx.y * BB * HIDDEN_C + (size_t)h0) * SEQ_C;
    const size_t bstride = (size_t)HIDDEN_C * SEQ_C;
    const uint32_t rbase[2] = { smem_u32(ring[0]), smem_u32(ring[1]) };

    // ---- Prologue: async-copy chunks 0 and 1 (16 x 1 KB tile copies each) ----
    if (t < 16) {
        const uint32_t dst_off = (uint32_t)t * (TPAD * 4);
        {
            const float* src = x + chunk0 + (size_t)t * 256;
            mbar_expect_tx(bar0, TILE_BYTES);
            bulk_g2s(rbase[0] + dst_off, src, TILE_BYTES, bar0);
        }
        {
            const float* src = x + chunk0 + bstride + (size_t)t * 256;
            mbar_expect_tx(bar1, TILE_BYTES);
            bulk_g2s(rbase[1] + dst_off, src, TILE_BYTES, bar1);
        }
    }

    #pragma unroll 1
    for (int bi = 0; bi < BB; bi++) {
        const int s = bi & 1;
        const uint32_t bar = s ? bar1 : bar0;
        mbar_wait(bar, (bi >> 1) & 1);

        // ---- Compute: 4x4 register tile; x from ring[s], W from registers ----
        const float4* x4 = reinterpret_cast<const float4*>(ring[s]) + hl * TPAD4 + gq;

        float acc[4][4];
        #pragma unroll
        for (int r = 0; r < 4; r++)
            #pragma unroll
            for (int c = 0; c < 4; c++)
                acc[r][c] = 0.0f;

        #pragma unroll
        for (int i = 0; i < 16; i++) {
            float4 xv = x4[i * 4];          // conflict-free LDS.128
            float4 wv = wreg[i];
            acc[0][0] = fmaf(wv.x, xv.x, acc[0][0]);
            acc[0][1] = fmaf(wv.x, xv.y, acc[0][1]);
            acc[0][2] = fmaf(wv.x, xv.z, acc[0][2]);
            acc[0][3] = fmaf(wv.x, xv.w, acc[0][3]);
            acc[1][0] = fmaf(wv.y, xv.x, acc[1][0]);
            acc[1][1] = fmaf(wv.y, xv.y, acc[1][1]);
            acc[1][2] = fmaf(wv.y, xv.z, acc[1][2]);
            acc[1][3] = fmaf(wv.y, xv.w, acc[1][3]);
            acc[2][0] = fmaf(wv.z, xv.x, acc[2][0]);
            acc[2][1] = fmaf(wv.z, xv.y, acc[2][1]);
            acc[2][2] = fmaf(wv.z, xv.z, acc[2][2]);
            acc[2][3] = fmaf(wv.z, xv.w, acc[2][3]);
            acc[3][0] = fmaf(wv.w, xv.x, acc[3][0]);
            acc[3][1] = fmaf(wv.w, xv.y, acc[3][1]);
            acc[3][2] = fmaf(wv.w, xv.z, acc[3][2]);
            acc[3][3] = fmaf(wv.w, xv.w, acc[3][3]);
        }

        // ---- Sector-dense streaming store: rows o=4oq+r, cols 4gq..4gq+3 ----
        {
            float* ybase = y + chunk0 + (size_t)bi * bstride
                         + (size_t)hl * 256 + (size_t)(4 * oq) * 16 + (size_t)(4 * gq);
            #pragma unroll
            for (int r = 0; r < 4; r++) {
                float4 v = make_float4(acc[r][0], acc[r][1], acc[r][2], acc[r][3]);
                __stcs(reinterpret_cast<float4*>(ybase + r * 16), v);
            }
        }

        __syncthreads();   // all reads of ring[s] done -> buffer reusable

        // ---- Issue async copy of chunk bi+2 into ring[s] ----
        if (bi + 2 < BB && t < 16) {
            const float* src = x + chunk0 + (size_t)(bi + 2) * bstride + (size_t)t * 256;
            mbar_expect_tx(bar, TILE_BYTES);
            bulk_g2s(rbase[s] + (uint32_t)t * (TPAD * 4), src, TILE_BYTES, bar);
        }
    }
}

extern "C" void kernel_launch(void* const* d_in, const int* in_sizes, int n_in,
                              void* d_out, int out_size)
{
    const float* x = (const float*)d_in[0];   // (B, 512, 1, 256) fp32
    const float* W = (const float*)d_in[1];   // (512, 16, 16) fp32
    float* y = (float*)d_out;

    const int B = in_sizes[0] / (HIDDEN_C * SEQ_C);   // 512

    dim3 grid(HIDDEN_C / HB, B / BB);   // (32, 64)
    global_mixer_kernel<<<grid, 256>>>(x, W, y);
}

// round 12
// speedup vs baseline: 11.4845x; 1.1079x over previous
#include <cuda_runtime.h>
#include <cstdint>

// y[b,h,o,g] = sum_i W[h,o,i] * x[b,h,i,g]
// x: (B=512, HIDDEN=512, SEQ=256) fp32; per (b,h) tile 16 i x 16 g, g fastest (1 KB).
// W: (HIDDEN, 16, 16) fp32.
//
// R11: per-warp decoupled pipelines. Each warp owns 2 h-tiles per chunk and a
// private 4-deep smem ring with private mbarriers; cp.async.bulk staging; no
// __syncthreads in the main loop. W register-cached (64 regs/thread).

#define HIDDEN_C 512
#define SEQ_C    256
#define HB       16            // h per block -> 8 warps x 2 tiles
#define BB       8             // b-chunks per block
#define DEPTH    4             // per-warp ring depth
#define SLOT_F4  132           // per-warp slot: tile0 @0 (64 f4), tile1 @68 f4
#define STAGE_F4 (8 * SLOT_F4) // 1056 f4 per stage (8 warps)
#define RING_BYTES (DEPTH * STAGE_F4 * 16)   // 67584
#define TILE_BYTES 1024u

__device__ __forceinline__ uint32_t smem_u32(const void* p) {
    uint32_t a;
    asm("{ .reg .u64 t; cvta.to.shared.u64 t, %1; cvt.u32.u64 %0, t; }" : "=r"(a) : "l"(p));
    return a;
}
__device__ __forceinline__ void mbar_init(uint32_t bar, uint32_t count) {
    asm volatile("mbarrier.init.shared.b64 [%0], %1;" :: "r"(bar), "r"(count) : "memory");
}
__device__ __forceinline__ void mbar_expect_tx(uint32_t bar, uint32_t bytes) {
    asm volatile("mbarrier.arrive.expect_tx.shared.b64 _, [%0], %1;"
                 :: "r"(bar), "r"(bytes) : "memory");
}
__device__ __forceinline__ void bulk_g2s(uint32_t dst, const void* src, uint32_t bytes,
                                         uint32_t bar) {
    asm volatile(
        "cp.async.bulk.shared::cluster.global.mbarrier::complete_tx::bytes "
        "[%0], [%1], %2, [%3];"
        :: "r"(dst), "l"(src), "r"(bytes), "r"(bar) : "memory");
}
__device__ __forceinline__ void mbar_wait(uint32_t bar, uint32_t parity) {
    asm volatile(
        "{\n\t"
        ".reg .pred P;\n\t"
        "W_%=:\n\t"
        "mbarrier.try_wait.parity.acquire.cta.shared::cta.b64 P, [%0], %1, 0x989680;\n\t"
        "@P bra D_%=;\n\t"
        "bra W_%=;\n\t"
        "D_%=:\n\t"
        "}"
        :: "r"(bar), "r"(parity) : "memory");
}
__device__ __forceinline__ void fence_proxy_async_cta() {
    asm volatile("fence.proxy.async.shared::cta;" ::: "memory");
}

extern __shared__ float dyn_smem[];   // RING_BYTES

__global__ __launch_bounds__(256, 2)
void global_mixer_kernel(const float* __restrict__ x,
                         const float* __restrict__ W,
                         float* __restrict__ y)
{
    __shared__ __align__(8) unsigned long long mbar[DEPTH][8];

    const int t  = threadIdx.x;      // 256
    const int h0 = blockIdx.x * HB;

    const int w   = t >> 5;          // warp 0..7
    const int l   = t & 31;
    const int hlo = l >> 4;          // 0/1: which of this warp's two tiles
    const int oq  = (l >> 2) & 3;
    const int gq  = l & 3;
    const int hl  = 2 * w + hlo;     // h within block

    // ---- Stage W^T into dyn_smem (stride 272 floats, conflict-free), pull wreg ----
    {
        const int shl = t >> 4;
        const int so  = t & 15;
        const float4* wr =
            reinterpret_cast<const float4*>(W + ((size_t)(h0 + shl)) * 256 + (size_t)so * 16);
        float4 w0 = wr[0], w1 = wr[1], w2 = wr[2], w3 = wr[3];
        float wrow[16] = { w0.x, w0.y, w0.z, w0.w,
                           w1.x, w1.y, w1.z, w1.w,
                           w2.x, w2.y, w2.z, w2.w,
                           w3.x, w3.y, w3.z, w3.w };
        float* dst = &dyn_smem[shl * 272 + so];
        #pragma unroll
        for (int i = 0; i < 16; i++)
            dst[i * 16] = wrow[i];
    }
    __syncthreads();

    float4 wreg[16];
    {
        // wreg[i] = W[h0+hl][4oq..4oq+3][i]
        const float4* wsrc = reinterpret_cast<const float4*>(dyn_smem) + hl * 68 + oq;
        #pragma unroll
        for (int i = 0; i < 16; i++)
            wreg[i] = wsrc[i * 4];
    }
    __syncthreads();                  // dyn_smem free for the x ring

    // ---- Per-warp barriers + prologue copies (chunks 0..DEPTH-1) ----
    const size_t chunk0  = ((size_t)blockIdx.y * BB * HIDDEN_C + (size_t)h0) * SEQ_C;
    const size_t bstride = (size_t)HIDDEN_C * SEQ_C;
    const uint32_t ring0 = smem_u32(dyn_smem);

    uint32_t mybar[DEPTH];
    #pragma unroll
    for (int s = 0; s < DEPTH; s++)
        mybar[s] = smem_u32(&mbar[s][w]);

    if (l == 0) {
        #pragma unroll
        for (int s = 0; s < DEPTH; s++)
            mbar_init(mybar[s], 1);
        fence_proxy_async_cta();
        #pragma unroll
        for (int s = 0; s < DEPTH; s++) {
            const uint32_t dst = ring0 + (uint32_t)(s * STAGE_F4 + w * SLOT_F4) * 16;
            const float*   src = x + chunk0 + (size_t)s * bstride + (size_t)(2 * w) * 256;
            mbar_expect_tx(mybar[s], 2 * TILE_BYTES);
            bulk_g2s(dst,        src,       TILE_BYTES, mybar[s]);
            bulk_g2s(dst + 1088, src + 256, TILE_BYTES, mybar[s]);
        }
    }
    __syncwarp();

    const float4* xbase = reinterpret_cast<const float4*>(dyn_smem)
                        + w * SLOT_F4 + hlo * 68 + gq;

    #pragma unroll 1
    for (int bi = 0; bi < BB; bi++) {
        const int s = bi & (DEPTH - 1);
        mbar_wait(mybar[s], (bi >> 2) & 1);

        const float4* x4 = xbase + s * STAGE_F4;

        float acc[4][4];
        #pragma unroll
        for (int r = 0; r < 4; r++)
            #pragma unroll
            for (int c = 0; c < 4; c++)
                acc[r][c] = 0.0f;

        #pragma unroll
        for (int i = 0; i < 16; i++) {
            float4 xv = x4[i * 4];           // conflict-free LDS.128
            float4 wv = wreg[i];
            acc[0][0] = fmaf(wv.x, xv.x, acc[0][0]);
            acc[0][1] = fmaf(wv.x, xv.y, acc[0][1]);
            acc[0][2] = fmaf(wv.x, xv.z, acc[0][2]);
            acc[0][3] = fmaf(wv.x, xv.w, acc[0][3]);
            acc[1][0] = fmaf(wv.y, xv.x, acc[1][0]);
            acc[1][1] = fmaf(wv.y, xv.y, acc[1][1]);
            acc[1][2] = fmaf(wv.y, xv.z, acc[1][2]);
            acc[1][3] = fmaf(wv.y, xv.w, acc[1][3]);
            acc[2][0] = fmaf(wv.z, xv.x, acc[2][0]);
            acc[2][1] = fmaf(wv.z, xv.y, acc[2][1]);
            acc[2][2] = fmaf(wv.z, xv.z, acc[2][2]);
            acc[2][3] = fmaf(wv.z, xv.w, acc[2][3]);
            acc[3][0] = fmaf(wv.w, xv.x, acc[3][0]);
            acc[3][1] = fmaf(wv.w, xv.y, acc[3][1]);
            acc[3][2] = fmaf(wv.w, xv.z, acc[3][2]);
            acc[3][3] = fmaf(wv.w, xv.w, acc[3][3]);
        }

        // ---- Sector-dense streaming store ----
        {
            float* ybase = y + chunk0 + (size_t)bi * bstride
                         + (size_t)hl * 256 + (size_t)(4 * oq) * 16 + (size_t)(4 * gq);
            #pragma unroll
            for (int r = 0; r < 4; r++) {
                float4 v = make_float4(acc[r][0], acc[r][1], acc[r][2], acc[r][3]);
                __stcs(reinterpret_cast<float4*>(ybase + r * 16), v);
            }
        }

        __syncwarp();   // whole warp done reading slot s

        // ---- Refill slot s with chunk bi+DEPTH ----
        if (bi + DEPTH < BB && l == 0) {
            fence_proxy_async_cta();   // order generic reads before async rewrite
            const uint32_t dst = ring0 + (uint32_t)(s * STAGE_F4 + w * SLOT_F4) * 16;
            const float*   src = x + chunk0 + (size_t)(bi + DEPTH) * bstride
                               + (size_t)(2 * w) * 256;
            mbar_expect_tx(mybar[s], 2 * TILE_BYTES);
            bulk_g2s(dst,        src,       TILE_BYTES, mybar[s]);
            bulk_g2s(dst + 1088, src + 256, TILE_BYTES, mybar[s]);
        }
    }
}

extern "C" void kernel_launch(void* const* d_in, const int* in_sizes, int n_in,
                              void* d_out, int out_size)
{
    const float* x = (const float*)d_in[0];   // (B, 512, 1, 256) fp32
    const float* W = (const float*)d_in[1];   // (512, 16, 16) fp32
    float* y = (float*)d_out;

    const int B = in_sizes[0] / (HIDDEN_C * SEQ_C);   // 512

    cudaFuncSetAttribute(global_mixer_kernel,
                         cudaFuncAttributeMaxDynamicSharedMemorySize, RING_BYTES);

    dim3 grid(HIDDEN_C / HB, B / BB);   // (32, 64)
    global_mixer_kernel<<<grid, 256, RING_BYTES>>>(x, W, y);
}

// round 14
// speedup vs baseline: 11.5355x; 1.0044x over previous
#include <cuda_runtime.h>
#include <cstdint>

// y[b,h,o,g] = sum_i W[h,o,i] * x[b,h,i,g]
// x: (B=512, HIDDEN=512, SEQ=256) fp32; per (b,h) tile 16 i x 16 g, g fastest (1 KB).
// W: (HIDDEN, 16, 16) fp32.
//
// R12: R11 (per-warp decoupled 4-deep cp.async.bulk pipelines, W in registers)
// + refill issued BEFORE the output stores + strength-reduced addressing.

#define HIDDEN_C 512
#define SEQ_C    256
#define HB       16            // h per block -> 8 warps x 2 tiles
#define BB       8             // b-chunks per block
#define DEPTH    4             // per-warp ring depth
#define SLOT_F4  132           // per-warp slot: tile0 @0, tile1 @68 f4 (bank-group shifted)
#define STAGE_F4 (8 * SLOT_F4) // 1056 f4 per stage
#define STAGE_B  (STAGE_F4 * 16)             // 16896 bytes
#define RING_BYTES (DEPTH * STAGE_B)         // 67584
#define TILE_BYTES 1024u

__device__ __forceinline__ uint32_t smem_u32(const void* p) {
    uint32_t a;
    asm("{ .reg .u64 t; cvta.to.shared.u64 t, %1; cvt.u32.u64 %0, t; }" : "=r"(a) : "l"(p));
    return a;
}
__device__ __forceinline__ void mbar_init(uint32_t bar, uint32_t count) {
    asm volatile("mbarrier.init.shared.b64 [%0], %1;" :: "r"(bar), "r"(count) : "memory");
}
__device__ __forceinline__ void mbar_expect_tx(uint32_t bar, uint32_t bytes) {
    asm volatile("mbarrier.arrive.expect_tx.shared.b64 _, [%0], %1;"
                 :: "r"(bar), "r"(bytes) : "memory");
}
__device__ __forceinline__ void bulk_g2s(uint32_t dst, const void* src, uint32_t bytes,
                                         uint32_t bar) {
    asm volatile(
        "cp.async.bulk.shared::cluster.global.mbarrier::complete_tx::bytes "
        "[%0], [%1], %2, [%3];"
        :: "r"(dst), "l"(src), "r"(bytes), "r"(bar) : "memory");
}
__device__ __forceinline__ void mbar_wait(uint32_t bar, uint32_t parity) {
    asm volatile(
        "{\n\t"
        ".reg .pred P;\n\t"
        "W_%=:\n\t"
        "mbarrier.try_wait.parity.acquire.cta.shared::cta.b64 P, [%0], %1, 0x989680;\n\t"
        "@P bra D_%=;\n\t"
        "bra W_%=;\n\t"
        "D_%=:\n\t"
        "}"
        :: "r"(bar), "r"(parity) : "memory");
}
__device__ __forceinline__ void fence_proxy_async_cta() {
    asm volatile("fence.proxy.async.shared::cta;" ::: "memory");
}

extern __shared__ float dyn_smem[];   // RING_BYTES

__global__ __launch_bounds__(256, 2)
void global_mixer_kernel(const float* __restrict__ x,
                         const float* __restrict__ W,
                         float* __restrict__ y)
{
    __shared__ __align__(8) unsigned long long mbar[DEPTH][8];

    const int t  = threadIdx.x;      // 256
    const int h0 = blockIdx.x * HB;

    const int w   = t >> 5;          // warp 0..7
    const int l   = t & 31;
    const int hlo = l >> 4;          // which of this warp's two tiles
    const int oq  = (l >> 2) & 3;
    const int gq  = l & 3;
    const int hl  = 2 * w + hlo;

    // ---- Stage W^T through smem, pull this thread's 16 W-columns into regs ----
    {
        const int shl = t >> 4;
        const int so  = t & 15;
        const float4* wr =
            reinterpret_cast<const float4*>(W + ((size_t)(h0 + shl)) * 256 + (size_t)so * 16);
        float4 w0 = wr[0], w1 = wr[1], w2 = wr[2], w3 = wr[3];
        float wrow[16] = { w0.x, w0.y, w0.z, w0.w,
                           w1.x, w1.y, w1.z, w1.w,
                           w2.x, w2.y, w2.z, w2.w,
                           w3.x, w3.y, w3.z, w3.w };
        float* dst = &dyn_smem[shl * 272 + so];
        #pragma unroll
        for (int i = 0; i < 16; i++)
            dst[i * 16] = wrow[i];
    }
    __syncthreads();

    float4 wreg[16];
    {
        const float4* wsrc = reinterpret_cast<const float4*>(dyn_smem) + hl * 68 + oq;
        #pragma unroll
        for (int i = 0; i < 16; i++)
            wreg[i] = wsrc[i * 4];          // wreg[i] = W[h][4oq..4oq+3][i]
    }
    __syncthreads();                         // dyn_smem free for the x ring

    // ---- Per-warp barriers + prologue (chunks 0..DEPTH-1) ----
    const size_t chunk0  = ((size_t)blockIdx.y * BB * HIDDEN_C + (size_t)h0) * SEQ_C;
    const size_t bstride = (size_t)HIDDEN_C * SEQ_C;
    const uint32_t ring0 = smem_u32(dyn_smem);
    const uint32_t wslot0 = ring0 + (uint32_t)(w * SLOT_F4) * 16;  // slot s: + s*STAGE_B

    uint32_t mybar[DEPTH];
    #pragma unroll
    for (int s = 0; s < DEPTH; s++)
        mybar[s] = smem_u32(&mbar[s][w]);

    if (l == 0) {
        #pragma unroll
        for (int s = 0; s < DEPTH; s++)
            mbar_init(mybar[s], 1);
        fence_proxy_async_cta();
        const float* src = x + chunk0 + (size_t)(2 * w) * 256;
        #pragma unroll
        for (int s = 0; s < DEPTH; s++) {
            const uint32_t dst = wslot0 + (uint32_t)s * STAGE_B;
            mbar_expect_tx(mybar[s], 2 * TILE_BYTES);
            bulk_g2s(dst,        src,       TILE_BYTES, mybar[s]);
            bulk_g2s(dst + 1088, src + 256, TILE_BYTES, mybar[s]);
            src += bstride;
        }
    }
    __syncwarp();

    const float4* xbase = reinterpret_cast<const float4*>(dyn_smem)
                        + w * SLOT_F4 + hlo * 68 + gq;

    // running pointers (strength-reduced)
    float* yptr = y + chunk0 + (size_t)hl * 256 + (size_t)(4 * oq) * 16 + (size_t)(4 * gq);
    const float* xrefill = x + chunk0 + (size_t)DEPTH * bstride + (size_t)(2 * w) * 256;

    #pragma unroll 1
    for (int bi = 0; bi < BB; bi++) {
        const int s = bi & (DEPTH - 1);
        mbar_wait(mybar[s], (bi >> 2) & 1);

        const float4* x4 = xbase + s * STAGE_F4;

        float acc[4][4];
        #pragma unroll
        for (int r = 0; r < 4; r++)
            #pragma unroll
            for (int c = 0; c < 4; c++)
                acc[r][c] = 0.0f;

        #pragma unroll
        for (int i = 0; i < 16; i++) {
            float4 xv = x4[i * 4];           // conflict-free LDS.128
            float4 wv = wreg[i];
            acc[0][0] = fmaf(wv.x, xv.x, acc[0][0]);
            acc[0][1] = fmaf(wv.x, xv.y, acc[0][1]);
            acc[0][2] = fmaf(wv.x, xv.z, acc[0][2]);
            acc[0][3] = fmaf(wv.x, xv.w, acc[0][3]);
            acc[1][0] = fmaf(wv.y, xv.x, acc[1][0]);
            acc[1][1] = fmaf(wv.y, xv.y, acc[1][1]);
            acc[1][2] = fmaf(wv.y, xv.z, acc[1][2]);
            acc[1][3] = fmaf(wv.y, xv.w, acc[1][3]);
            acc[2][0] = fmaf(wv.z, xv.x, acc[2][0]);
            acc[2][1] = fmaf(wv.z, xv.y, acc[2][1]);
            acc[2][2] = fmaf(wv.z, xv.z, acc[2][2]);
            acc[2][3] = fmaf(wv.z, xv.w, acc[2][3]);
            acc[3][0] = fmaf(wv.w, xv.x, acc[3][0]);
            acc[3][1] = fmaf(wv.w, xv.y, acc[3][1]);
            acc[3][2] = fmaf(wv.w, xv.z, acc[3][2]);
            acc[3][3] = fmaf(wv.w, xv.w, acc[3][3]);
        }

        // ---- Refill slot s FIRST (all reads of it are done), then store ----
        __syncwarp();
        if (bi + DEPTH < BB && l == 0) {
            fence_proxy_async_cta();         // order generic reads before async rewrite
            const uint32_t dst = wslot0 + (uint32_t)s * STAGE_B;
            mbar_expect_tx(mybar[s], 2 * TILE_BYTES);
            bulk_g2s(dst,        xrefill,       TILE_BYTES, mybar[s]);
            bulk_g2s(dst + 1088, xrefill + 256, TILE_BYTES, mybar[s]);
        }
        xrefill += bstride;

        // ---- Sector-dense streaming store ----
        #pragma unroll
        for (int r = 0; r < 4; r++) {
            float4 v = make_float4(acc[r][0], acc[r][1], acc[r][2], acc[r][3]);
            __stcs(reinterpret_cast<float4*>(yptr + r * 16), v);
        }
        yptr += bstride;
    }
}

extern "C" void kernel_launch(void* const* d_in, const int* in_sizes, int n_in,
                              void* d_out, int out_size)
{
    const float* x = (const float*)d_in[0];   // (B, 512, 1, 256) fp32
    const float* W = (const float*)d_in[1];   // (512, 16, 16) fp32
    float* y = (float*)d_out;

    const int B = in_sizes[0] / (HIDDEN_C * SEQ_C);   // 512

    cudaFuncSetAttribute(global_mixer_kernel,
                         cudaFuncAttributeMaxDynamicSharedMemorySize, RING_BYTES);

    dim3 grid(HIDDEN_C / HB, B / BB);   // (32, 64)
    global_mixer_kernel<<<grid, 256, RING_BYTES>>>(x, W, y);
}

// round 15
// speedup vs baseline: 11.6345x; 1.0086x over previous
#include <cuda_runtime.h>
#include <cstdint>

// y[b,h,o,g] = sum_i W[h,o,i] * x[b,h,i,g]
// x: (B=512, HIDDEN=512, SEQ=256) fp32; per (b,h) tile 16 i x 16 g, g fastest (1 KB).
// W: (HIDDEN, 16, 16) fp32.
//
// R14: R12 pipeline (per-warp decoupled 4-deep cp.async.bulk rings, W in regs)
// + packed fma.rn.f32x2 inner loop: 8 FFMA2 + 4 packs per i instead of 16 FFMA.
// Halves FMA-pipe occupancy (58us -> 29us/SM), exposing the DRAM floor.

#define HIDDEN_C 512
#define SEQ_C    256
#define HB       16            // h per block -> 8 warps x 2 tiles
#define BB       8             // b-chunks per block
#define DEPTH    4             // per-warp ring depth
#define SLOT_F4  132           // per-warp slot: tile0 @0, tile1 @68 f4
#define STAGE_F4 (8 * SLOT_F4) // 1056 f4 per stage
#define STAGE_B  (STAGE_F4 * 16)             // 16896 bytes
#define RING_BYTES (DEPTH * STAGE_B)         // 67584
#define TILE_BYTES 1024u

typedef unsigned long long u64;

__device__ __forceinline__ uint32_t smem_u32(const void* p) {
    uint32_t a;
    asm("{ .reg .u64 t; cvta.to.shared.u64 t, %1; cvt.u32.u64 %0, t; }" : "=r"(a) : "l"(p));
    return a;
}
__device__ __forceinline__ void mbar_init(uint32_t bar, uint32_t count) {
    asm volatile("mbarrier.init.shared.b64 [%0], %1;" :: "r"(bar), "r"(count) : "memory");
}
__device__ __forceinline__ void mbar_expect_tx(uint32_t bar, uint32_t bytes) {
    asm volatile("mbarrier.arrive.expect_tx.shared.b64 _, [%0], %1;"
                 :: "r"(bar), "r"(bytes) : "memory");
}
__device__ __forceinline__ void bulk_g2s(uint32_t dst, const void* src, uint32_t bytes,
                                         uint32_t bar) {
    asm volatile(
        "cp.async.bulk.shared::cluster.global.mbarrier::complete_tx::bytes "
        "[%0], [%1], %2, [%3];"
        :: "r"(dst), "l"(src), "r"(bytes), "r"(bar) : "memory");
}
__device__ __forceinline__ void mbar_wait(uint32_t bar, uint32_t parity) {
    asm volatile(
        "{\n\t"
        ".reg .pred P;\n\t"
        "W_%=:\n\t"
        "mbarrier.try_wait.parity.acquire.cta.shared::cta.b64 P, [%0], %1, 0x989680;\n\t"
        "@P bra D_%=;\n\t"
        "bra W_%=;\n\t"
        "D_%=:\n\t"
        "}"
        :: "r"(bar), "r"(parity) : "memory");
}
__device__ __forceinline__ void fence_proxy_async_cta() {
    asm volatile("fence.proxy.async.shared::cta;" ::: "memory");
}

// packed f32x2 helpers
#define FMA2(d, a, b, c) \
    asm("fma.rn.f32x2 %0, %1, %2, %3;" : "=l"(d) : "l"(a), "l"(b), "l"(c))
#define PACK2(d, lo, hi) \
    asm("mov.b64 %0, {%1, %2};" : "=l"(d) : "f"(lo), "f"(hi))
#define UNPACK2(lo, hi, s) \
    asm("mov.b64 {%0, %1}, %2;" : "=f"(lo), "=f"(hi) : "l"(s))

extern __shared__ float dyn_smem[];   // RING_BYTES

__global__ __launch_bounds__(256, 2)
void global_mixer_kernel(const float* __restrict__ x,
                         const float* __restrict__ W,
                         float* __restrict__ y)
{
    __shared__ __align__(8) unsigned long long mbar[DEPTH][8];

    const int t  = threadIdx.x;      // 256
    const int h0 = blockIdx.x * HB;

    const int w   = t >> 5;          // warp 0..7
    const int l   = t & 31;
    const int hlo = l >> 4;          // which of this warp's two tiles
    const int oq  = (l >> 2) & 3;
    const int gq  = l & 3;
    const int hl  = 2 * w + hlo;

    // ---- Stage W^T through smem; pack this thread's W columns as f32x2 o-pairs ----
    {
        const int shl = t >> 4;
        const int so  = t & 15;
        const float4* wr =
            reinterpret_cast<const float4*>(W + ((size_t)(h0 + shl)) * 256 + (size_t)so * 16);
        float4 w0 = wr[0], w1 = wr[1], w2 = wr[2], w3 = wr[3];
        float wrow[16] = { w0.x, w0.y, w0.z, w0.w,
                           w1.x, w1.y, w1.z, w1.w,
                           w2.x, w2.y, w2.z, w2.w,
                           w3.x, w3.y, w3.z, w3.w };
        float* dst = &dyn_smem[shl * 272 + so];
        #pragma unroll
        for (int i = 0; i < 16; i++)
            dst[i * 16] = wrow[i];
    }
    __syncthreads();

    u64 wpk[16][2];   // wpk[i][0]={W[4oq,i],W[4oq+1,i]}, [1]={W[4oq+2,i],W[4oq+3,i]}
    {
        const float4* wsrc = reinterpret_cast<const float4*>(dyn_smem) + hl * 68 + oq;
        #pragma unroll
        for (int i = 0; i < 16; i++) {
            float4 wv = wsrc[i * 4];
            PACK2(wpk[i][0], wv.x, wv.y);
            PACK2(wpk[i][1], wv.z, wv.w);
        }
    }
    __syncthreads();                 // dyn_smem free for the x ring

    // ---- Per-warp barriers + prologue (chunks 0..DEPTH-1) ----
    const size_t chunk0  = ((size_t)blockIdx.y * BB * HIDDEN_C + (size_t)h0) * SEQ_C;
    const size_t bstride = (size_t)HIDDEN_C * SEQ_C;
    const uint32_t ring0 = smem_u32(dyn_smem);
    const uint32_t wslot0 = ring0 + (uint32_t)(w * SLOT_F4) * 16;

    uint32_t mybar[DEPTH];
    #pragma unroll
    for (int s = 0; s < DEPTH; s++)
        mybar[s] = smem_u32(&mbar[s][w]);

    if (l == 0) {
        #pragma unroll
        for (int s = 0; s < DEPTH; s++)
            mbar_init(mybar[s], 1);
        fence_proxy_async_cta();
        const float* src = x + chunk0 + (size_t)(2 * w) * 256;
        #pragma unroll
        for (int s = 0; s < DEPTH; s++) {
            const uint32_t dst = wslot0 + (uint32_t)s * STAGE_B;
            mbar_expect_tx(mybar[s], 2 * TILE_BYTES);
            bulk_g2s(dst,        src,       TILE_BYTES, mybar[s]);
            bulk_g2s(dst + 1088, src + 256, TILE_BYTES, mybar[s]);
            src += bstride;
        }
    }
    __syncwarp();

    const float4* xbase = reinterpret_cast<const float4*>(dyn_smem)
                        + w * SLOT_F4 + hlo * 68 + gq;

    float* yptr = y + chunk0 + (size_t)hl * 256 + (size_t)(4 * oq) * 16 + (size_t)(4 * gq);
    const float* xrefill = x + chunk0 + (size_t)DEPTH * bstride + (size_t)(2 * w) * 256;

    #pragma unroll 1
    for (int bi = 0; bi < BB; bi++) {
        const int s = bi & (DEPTH - 1);
        mbar_wait(mybar[s], (bi >> 2) & 1);

        const float4* x4 = xbase + s * STAGE_F4;

        // acc2[p][c]: lanes = o rows (4oq+2p, 4oq+2p+1), column c = g (4gq+c)
        u64 acc2[2][4];
        #pragma unroll
        for (int p = 0; p < 2; p++)
            #pragma unroll
            for (int c = 0; c < 4; c++)
                acc2[p][c] = 0ull;

        #pragma unroll
        for (int i = 0; i < 16; i++) {
            float4 xv = x4[i * 4];           // conflict-free LDS.128
            u64 x0, x1, x2, x3;
            PACK2(x0, xv.x, xv.x);
            PACK2(x1, xv.y, xv.y);
            PACK2(x2, xv.z, xv.z);
            PACK2(x3, xv.w, xv.w);
            u64 wlo = wpk[i][0], whi = wpk[i][1];
            FMA2(acc2[0][0], wlo, x0, acc2[0][0]);
            FMA2(acc2[1][0], whi, x0, acc2[1][0]);
            FMA2(acc2[0][1], wlo, x1, acc2[0][1]);
            FMA2(acc2[1][1], whi, x1, acc2[1][1]);
            FMA2(acc2[0][2], wlo, x2, acc2[0][2]);
            FMA2(acc2[1][2], whi, x2, acc2[1][2]);
            FMA2(acc2[0][3], wlo, x3, acc2[0][3]);
            FMA2(acc2[1][3], whi, x3, acc2[1][3]);
        }

        // ---- Refill slot s FIRST (all reads done), then store ----
        __syncwarp();
        if (bi + DEPTH < BB && l == 0) {
            fence_proxy_async_cta();
            const uint32_t dst = wslot0 + (uint32_t)s * STAGE_B;
            mbar_expect_tx(mybar[s], 2 * TILE_BYTES);
            bulk_g2s(dst,        xrefill,       TILE_BYTES, mybar[s]);
            bulk_g2s(dst + 1088, xrefill + 256, TILE_BYTES, mybar[s]);
        }
        xrefill += bstride;

        // ---- Unpack (register-aliasing movs) + sector-dense streaming store ----
        float rowv[4][4];
        #pragma unroll
        for (int p = 0; p < 2; p++)
            #pragma unroll
            for (int c = 0; c < 4; c++) {
                float lo, hi;
                UNPACK2(lo, hi, acc2[p][c]);
                rowv[2 * p + 0][c] = lo;
                rowv[2 * p + 1][c] = hi;
            }

        #pragma unroll
        for (int r = 0; r < 4; r++) {
            float4 v = make_float4(rowv[r][0], rowv[r][1], rowv[r][2], rowv[r][3]);
            __stcs(reinterpret_cast<float4*>(yptr + r * 16), v);
        }
        yptr += bstride;
    }
}

extern "C" void kernel_launch(void* const* d_in, const int* in_sizes, int n_in,
                              void* d_out, int out_size)
{
    const float* x = (const float*)d_in[0];   // (B, 512, 1, 256) fp32
    const float* W = (const float*)d_in[1];   // (512, 16, 16) fp32
    float* y = (float*)d_out;

    const int B = in_sizes[0] / (HIDDEN_C * SEQ_C);   // 512

    cudaFuncSetAttribute(global_mixer_kernel,
                         cudaFuncAttributeMaxDynamicSharedMemorySize, RING_BYTES);

    dim3 grid(HIDDEN_C / HB, B / BB);   // (32, 64)
    global_mixer_kernel<<<grid, 256, RING_BYTES>>>(x, W, y);
}